// round 8
// baseline (speedup 1.0000x reference)
#include <cuda_runtime.h>
#include <cstdint>

// LocalNorm2d: 32x32 box-filter local normalization, reflect padding.
// x: (32,3,512,512) fp32 -> out same shape.
//
// R8 = R7 with the staging-row index bug fixed (stage_row now loads the row
// it is told to, rmap(row), instead of rmap(row-16)).
//
//   - block = 192 threads = 6 warps = the 6 column-groups of one
//     (64-row segment, image) strip; grid = (8, 96)
//   - incoming padded row (i+16) staged into a 5-slot smem ring via
//     cp.async.cg, prefetch distance 4 rows -> DRAM latency (~577cyc) off
//     the warp scoreboard; xn becomes a 29-cyc LDS
//   - xo (row i-16) / xc (row i) stay global (L1/L2-hot), issued BEFORE the
//     per-row wait_group+__syncthreads so their latency hides under it
//   - horizontal 32-window via in-warp shfl segment sums

namespace {
constexpr int Hh    = 512;
constexpr int Ww    = 512;
constexpr int KSZ   = 32;
constexpr int PD    = 16;
constexpr int RSEG  = 64;          // output rows per block
constexpr int NSEG  = Hh / RSEG;   // 8
constexpr int WOUT  = 96;          // output cols per warp
constexpr int NCG   = 6;           // column groups = warps per block
constexpr int NT    = NCG * 32;    // 192
constexpr int NIMG  = 32 * 3;
constexpr int NSLOT = 5;           // smem ring slots
constexpr int PFD   = 4;           // prefetch distance (rows)
}

__device__ __forceinline__ int rmap(int q) {   // reflect into [0, 511]
    q = q < 0 ? -q : q;
    return q > (Ww - 1) ? 2 * (Ww - 1) - q : q;
}

// v = (x - mean)/std on raw sums: (1024*x - S) * rsqrt(|1024*Q - S^2|)
__device__ __forceinline__ float norm1(float ws, float wq, float xc) {
    float V  = fabsf(fmaf(-ws, ws, 1024.0f * wq));
    float rs = __frsqrt_rn(fmaxf(V, 1e-12f));
    float v  = fmaf(1024.0f, xc, -ws) * rs;
    return fminf(6.0f, fmaxf(-6.0f, v));
}

// Stage ORIGINAL row rmap(row) (512 floats) into ringrow as 128x16B cp.async.
__device__ __forceinline__ void stage_row(const float* __restrict__ xin,
                                          float* ringrow, int row, int tid) {
    if (tid < 128) {
        const float* src = xin + (size_t)rmap(row) * Ww + tid * 4;
        uint32_t dst = (uint32_t)__cvta_generic_to_shared(ringrow + tid * 4);
        asm volatile("cp.async.cg.shared.global [%0], [%1], 16;\n"
                     :: "r"(dst), "l"(src));
    }
    asm volatile("cp.async.commit_group;\n" ::);
}

__global__ __launch_bounds__(NT, 5)
void localnorm_kernel(const float* __restrict__ x, float* __restrict__ out)
{
    __shared__ float ring[NSLOT][Ww];   // 10240 B

    const int tid  = threadIdx.x;
    const int lane = tid & 31;
    const int cg   = tid >> 5;            // 0..5 (one warp per column group)
    const int seg  = blockIdx.x;          // 0..7
    const int img  = blockIdx.y;          // 0..95
    const int rstart = seg * RSEG;
    const int rend   = rstart + RSEG;

    const float* __restrict__ xin = x   + (size_t)img * (Hh * Ww);
    float*       __restrict__ op  = out + (size_t)img * (Hh * Ww);

    const int  c0       = cg * WOUT + 4 * lane;      // padded col base
    const bool interior = (c0 >= PD && c0 <= Ww + PD - 4);
    const int  off      = interior ? (c0 - PD) : 0;
    int cm0 = 0, cm1 = 0, cm2 = 0, cm3 = 0;
    if (!interior) {
        cm0 = rmap(c0 + 0 - PD); cm1 = rmap(c0 + 1 - PD);
        cm2 = rmap(c0 + 2 - PD); cm3 = rmap(c0 + 3 - PD);
    }
    const bool emit = (lane < 24) && (c0 < Ww);

    // ---- pre-issue staging: incoming rows for iterations rstart..rstart+3,
    //      i.e. original rows rmap(rstart+16+k) ----
    #pragma unroll
    for (int k = 0; k < PFD; ++k) {
        const int p = rstart + PD + k;            // row index (pre-reflect)
        stage_row(xin, ring[p % NSLOT], p, tid);
    }

    // ---- prologue: accumulate original rows rmap(rstart-16 .. rstart+15) ----
    float s0 = 0.f, s1 = 0.f, s2 = 0.f, s3 = 0.f;
    float q0 = 0.f, q1 = 0.f, q2 = 0.f, q3 = 0.f;
    #pragma unroll 2
    for (int p = rstart; p < rstart + KSZ; ++p) {
        const float* r = xin + (size_t)rmap(p - PD) * Ww + off;
        float4 v = interior ? *reinterpret_cast<const float4*>(r)
                            : make_float4(r[cm0], r[cm1], r[cm2], r[cm3]);
        s0 += v.x; s1 += v.y; s2 += v.z; s3 += v.w;
        q0 = fmaf(v.x, v.x, q0); q1 = fmaf(v.y, v.y, q1);
        q2 = fmaf(v.z, v.z, q2); q3 = fmaf(v.w, v.w, q3);
    }

    // ---- streaming pointers for the cache-hot global streams ----
    const float* po = xin + (size_t)rmap(rstart - PD) * Ww + off; // row rmap(i-16)
    const float* pc = xin + (size_t)rstart * Ww + c0;             // row i (center)
    float*       pw = op  + (size_t)rstart * Ww + c0;
    int dd = (rstart == 0) ? -Ww : Ww;
    const int flip_o = (rstart == 0) ? PD : 0x7fffffff;           // i == 16

    int slot  = (rstart + PD) % NSLOT;          // consume slot (row i+16)
    int pslot = (rstart + PD + PFD) % NSLOT;    // produce slot (row i+16+PFD)

    #pragma unroll 1
    for (int i = rstart; i < rend; ++i) {
        // cache-hot loads issued early: latency hides under wait+barrier
        float4 xo = interior ? *reinterpret_cast<const float4*>(po)
                             : make_float4(po[cm0], po[cm1], po[cm2], po[cm3]);
        float4 xc;
        if (emit) xc = *reinterpret_cast<const float4*>(pc);
        if (i == flip_o) dd = Ww;
        po += dd; pc += Ww;

        // this iteration's staged row is PFD groups back -> wait, publish
        asm volatile("cp.async.wait_group %0;\n" :: "n"(PFD - 1) : "memory");
        __syncthreads();

        // refill the pipeline: stage original row rmap(i+16+PFD)
        stage_row(xin, ring[pslot], i + PD + PFD, tid);
        pslot = (pslot + 1 == NSLOT) ? 0 : pslot + 1;

        // incoming row rmap(i+16) from smem ring
        const float* rr = ring[slot];
        float4 xn = interior ? *reinterpret_cast<const float4*>(rr + off)
                             : make_float4(rr[cm0], rr[cm1], rr[cm2], rr[cm3]);
        slot = (slot + 1 == NSLOT) ? 0 : slot + 1;

        // ---- horizontal window via in-warp shfl segment sums ----
        float i1 = s0 + s1, i2 = i1 + s2, i3 = i2 + s3;
        float j1 = q0 + q1, j2 = j1 + q2, j3 = j2 + q3;

        float as = i3 + __shfl_down_sync(0xFFFFFFFFu, i3, 1);
        float aq = j3 + __shfl_down_sync(0xFFFFFFFFu, j3, 1);
        as += __shfl_down_sync(0xFFFFFFFFu, as, 2);
        aq += __shfl_down_sync(0xFFFFFFFFu, aq, 2);
        float T8s = as + __shfl_down_sync(0xFFFFFFFFu, as, 4);
        float T8q = aq + __shfl_down_sync(0xFFFFFFFFu, aq, 4);

        float b1s = __shfl_down_sync(0xFFFFFFFFu, s0, 8);
        float b2s = __shfl_down_sync(0xFFFFFFFFu, i1, 8);
        float b3s = __shfl_down_sync(0xFFFFFFFFu, i2, 8);
        float b1q = __shfl_down_sync(0xFFFFFFFFu, q0, 8);
        float b2q = __shfl_down_sync(0xFFFFFFFFu, j1, 8);
        float b3q = __shfl_down_sync(0xFFFFFFFFu, j2, 8);

        if (emit) {
            float4 r;
            r.x = norm1(T8s,            T8q,            xc.x);
            r.y = norm1(T8s - s0 + b1s, T8q - q0 + b1q, xc.y);
            r.z = norm1(T8s - i1 + b2s, T8q - j1 + b2q, xc.z);
            r.w = norm1(T8s - i2 + b3s, T8q - j2 + b3q, xc.w);
            *reinterpret_cast<float4*>(pw) = r;
        }
        pw += Ww;

        // ---- slide vertical window ----
        s0 += xn.x - xo.x; s1 += xn.y - xo.y;
        s2 += xn.z - xo.z; s3 += xn.w - xo.w;
        q0 = fmaf(xn.x, xn.x, q0); q0 = fmaf(-xo.x, xo.x, q0);
        q1 = fmaf(xn.y, xn.y, q1); q1 = fmaf(-xo.y, xo.y, q1);
        q2 = fmaf(xn.z, xn.z, q2); q2 = fmaf(-xo.z, xo.z, q2);
        q3 = fmaf(xn.w, xn.w, q3); q3 = fmaf(-xo.w, xo.w, q3);
    }
}

extern "C" void kernel_launch(void* const* d_in, const int* in_sizes, int n_in,
                              void* d_out, int out_size) {
    const float* x = (const float*)d_in[0];
    float* out = (float*)d_out;
    (void)in_sizes; (void)n_in; (void)out_size;

    dim3 grid(NSEG, NIMG);   // (8, 96) = 768 blocks x 192 threads
    localnorm_kernel<<<grid, NT>>>(x, out);
}

// round 9
// speedup vs baseline: 1.3456x; 1.3456x over previous
#include <cuda_runtime.h>
#include <cstdint>

// LocalNorm2d: 32x32 box-filter local normalization, reflect padding.
// x: (32,3,512,512) fp32 -> out same shape.
//
// R9: R4 structure + WARP-PRIVATE cp.async ring for the incoming (DRAM-miss)
// row stream. No __syncthreads anywhere; one __syncwarp per row.
//   - each warp: 128 padded cols (4/thread) x 64 output rows
//   - incoming row rmap(i+16) staged 3 rows ahead into a private 4-slot smem
//     ring (32 lanes x 16B cp.async.cg) -> DRAM latency off the scoreboard
//   - xo (row i-16) / xc (row i) remain LDG (L2-hot, hidden by unroll)
//   - horizontal 32-window via in-warp shfl segment sums

namespace {
constexpr int Hh    = 512;
constexpr int Ww    = 512;
constexpr int KSZ   = 32;
constexpr int PD    = 16;
constexpr int RSEG  = 64;          // output rows per warp
constexpr int NSEG  = Hh / RSEG;   // 8
constexpr int WOUT  = 96;          // output cols per warp
constexpr int NCG   = 6;           // col groups per row band
constexpr int NWPB  = 8;           // warps per block
constexpr int NT    = NWPB * 32;   // 256
constexpr int NIMG  = 32 * 3;
constexpr int NSLOT = 4;           // warp-private ring slots (power of 2)
constexpr int PFD   = 3;           // prefetch distance (rows)
}

__device__ __forceinline__ int rmap(int q) {   // reflect into [0, 511]
    q = q < 0 ? -q : q;
    return q > (Ww - 1) ? 2 * (Ww - 1) - q : q;
}

// v = (x - mean)/std on raw sums: (1024*x - S) * rsqrt(|1024*Q - S^2|)
__device__ __forceinline__ float norm1(float ws, float wq, float xc) {
    float V  = fabsf(fmaf(-ws, ws, 1024.0f * wq));
    float rs = __frsqrt_rn(fmaxf(V, 1e-12f));
    float v  = fmaf(1024.0f, xc, -ws) * rs;
    return fminf(6.0f, fmaxf(-6.0f, v));
}

// All 32 lanes: copy 16B each -> 128 floats of original row into smem slot.
__device__ __forceinline__ void stage_row(const float* __restrict__ srcbase,
                                          float* dst_slot, int lane) {
    uint32_t d = (uint32_t)__cvta_generic_to_shared(dst_slot + lane * 4);
    asm volatile("cp.async.cg.shared.global [%0], [%1], 16;\n"
                 :: "r"(d), "l"(srcbase + lane * 4));
    asm volatile("cp.async.commit_group;\n" ::);
}

__global__ __launch_bounds__(NT, 4)
void localnorm_kernel(const float* __restrict__ x, float* __restrict__ out)
{
    __shared__ float ring[NWPB][NSLOT][128];   // 16 KB, warp-private rows

    const int lane = threadIdx.x & 31;
    const int wrp  = threadIdx.x >> 5;
    const int g    = blockIdx.x * NWPB + wrp;    // 0..47
    const int seg  = g / NCG;                    // 0..7
    const int cg   = g - seg * NCG;              // 0..5
    const int img  = blockIdx.y;

    const float* __restrict__ xin = x   + (size_t)img * (Hh * Ww);
    float*       __restrict__ op  = out + (size_t)img * (Hh * Ww);

    const int  c0       = cg * WOUT + 4 * lane;      // padded col base
    const bool interior = (c0 >= PD && c0 <= Ww + PD - 4);
    const int  off      = interior ? (c0 - PD) : 0;

    // warp's staged window of ORIGINAL columns: [sbase, sbase+128)
    const int sbase = (cg == 0) ? 0 : ((cg == NCG - 1) ? (Ww - 128)
                                                       : (cg * WOUT - PD));
    int cm0 = 0, cm1 = 0, cm2 = 0, cm3 = 0;
    if (!interior) {
        cm0 = rmap(c0 + 0 - PD); cm1 = rmap(c0 + 1 - PD);
        cm2 = rmap(c0 + 2 - PD); cm3 = rmap(c0 + 3 - PD);
    }
    // local (in-slot) offsets
    const int loff = off - sbase;                 // interior lanes
    const int lm0 = cm0 - sbase, lm1 = cm1 - sbase;
    const int lm2 = cm2 - sbase, lm3 = cm3 - sbase;

    const int  rstart = seg * RSEG;
    const int  rend   = rstart + RSEG;
    const bool emit   = (lane < 24) && (c0 < Ww);

    float* const wring = &ring[wrp][0][0];
    const float* const psrc = xin + sbase;        // staging source base

    // ---- pre-stage incoming rows for iterations rstart..rstart+2:
    //      original rows rmap(rstart+16+k) -> slot (rstart+k)&3 ----
    #pragma unroll
    for (int k = 0; k < PFD; ++k) {
        const int rq = rmap(rstart + PD + k);
        stage_row(psrc + (size_t)rq * Ww, wring + ((rstart + k) & 3) * 128, lane);
    }

    // ---- prologue: accumulate original rows rmap(rstart-16 .. rstart+15) ----
    float s0 = 0.f, s1 = 0.f, s2 = 0.f, s3 = 0.f;
    float q0 = 0.f, q1 = 0.f, q2 = 0.f, q3 = 0.f;
    #pragma unroll 2
    for (int p = rstart; p < rstart + KSZ; ++p) {
        const float* r = xin + (size_t)rmap(p - PD) * Ww + off;
        float4 v = interior ? *reinterpret_cast<const float4*>(r)
                            : make_float4(r[cm0], r[cm1], r[cm2], r[cm3]);
        s0 += v.x; s1 += v.y; s2 += v.z; s3 += v.w;
        q0 = fmaf(v.x, v.x, q0); q1 = fmaf(v.y, v.y, q1);
        q2 = fmaf(v.z, v.z, q2); q3 = fmaf(v.w, v.w, q3);
    }

    // ---- streaming pointers for the cache-hot streams ----
    const float* po = xin + (size_t)rmap(rstart - PD) * Ww + off; // row rmap(i-16)
    const float* pc = xin + (size_t)rstart * Ww + c0;             // row i (center)
    float*       pw = op  + (size_t)rstart * Ww + c0;
    int dd = (rstart == 0) ? -Ww : Ww;
    const int flip_o = (rstart == 0) ? PD : 0x7fffffff;           // i == 16

    #pragma unroll 2
    for (int i = rstart; i < rend; ++i) {
        // cache-hot loads issued early
        float4 xo = interior ? *reinterpret_cast<const float4*>(po)
                             : make_float4(po[cm0], po[cm1], po[cm2], po[cm3]);
        float4 xc;
        if (emit) xc = *reinterpret_cast<const float4*>(pc);
        if (i == flip_o) dd = Ww;
        po += dd; pc += Ww;

        // incoming row rmap(i+16) is PFD groups back in THIS warp's queue
        asm volatile("cp.async.wait_group %0;\n" :: "n"(PFD - 1) : "memory");
        __syncwarp();
        const float* rr = wring + (i & 3) * 128;
        float4 xn = interior ? *reinterpret_cast<const float4*>(rr + loff)
                             : make_float4(rr[lm0], rr[lm1], rr[lm2], rr[lm3]);

        // refill: stage original row rmap(i+16+PFD) into slot (i+PFD)&3
        {
            const int rq = rmap(i + PD + PFD);
            stage_row(psrc + (size_t)rq * Ww, wring + ((i + PFD) & 3) * 128, lane);
        }

        // ---- horizontal window via in-warp shfl segment sums ----
        float i1 = s0 + s1, i2 = i1 + s2, i3 = i2 + s3;
        float j1 = q0 + q1, j2 = j1 + q2, j3 = j2 + q3;

        float as = i3 + __shfl_down_sync(0xFFFFFFFFu, i3, 1);
        float aq = j3 + __shfl_down_sync(0xFFFFFFFFu, j3, 1);
        as += __shfl_down_sync(0xFFFFFFFFu, as, 2);
        aq += __shfl_down_sync(0xFFFFFFFFu, aq, 2);
        float T8s = as + __shfl_down_sync(0xFFFFFFFFu, as, 4);
        float T8q = aq + __shfl_down_sync(0xFFFFFFFFu, aq, 4);

        float b1s = __shfl_down_sync(0xFFFFFFFFu, s0, 8);
        float b2s = __shfl_down_sync(0xFFFFFFFFu, i1, 8);
        float b3s = __shfl_down_sync(0xFFFFFFFFu, i2, 8);
        float b1q = __shfl_down_sync(0xFFFFFFFFu, q0, 8);
        float b2q = __shfl_down_sync(0xFFFFFFFFu, j1, 8);
        float b3q = __shfl_down_sync(0xFFFFFFFFu, j2, 8);

        if (emit) {
            float4 r;
            r.x = norm1(T8s,            T8q,            xc.x);
            r.y = norm1(T8s - s0 + b1s, T8q - q0 + b1q, xc.y);
            r.z = norm1(T8s - i1 + b2s, T8q - j1 + b2q, xc.z);
            r.w = norm1(T8s - i2 + b3s, T8q - j2 + b3q, xc.w);
            *reinterpret_cast<float4*>(pw) = r;
        }
        pw += Ww;

        // ---- slide vertical window ----
        s0 += xn.x - xo.x; s1 += xn.y - xo.y;
        s2 += xn.z - xo.z; s3 += xn.w - xo.w;
        q0 = fmaf(xn.x, xn.x, q0); q0 = fmaf(-xo.x, xo.x, q0);
        q1 = fmaf(xn.y, xn.y, q1); q1 = fmaf(-xo.y, xo.y, q1);
        q2 = fmaf(xn.z, xn.z, q2); q2 = fmaf(-xo.z, xo.z, q2);
        q3 = fmaf(xn.w, xn.w, q3); q3 = fmaf(-xo.w, xo.w, q3);
    }

    // drain outstanding cp.asyncs before CTA exit (smem reuse safety)
    asm volatile("cp.async.wait_group 0;\n" ::: "memory");
}

extern "C" void kernel_launch(void* const* d_in, const int* in_sizes, int n_in,
                              void* d_out, int out_size) {
    const float* x = (const float*)d_in[0];
    float* out = (float*)d_out;
    (void)in_sizes; (void)n_in; (void)out_size;

    dim3 grid(NSEG * NCG / NWPB, NIMG);   // (6, 96) = 576 blocks
    localnorm_kernel<<<grid, NT>>>(x, out);
}